// round 16
// baseline (speedup 1.0000x reference)
#include <cuda_runtime.h>
#include <cuda_bf16.h>
#include <cstdint>

// ---------------------------------------------------------------------------
// Net_7335804141892: 3x GCSConv (out = relu(A@(xW1) + xW2 + b)) -> global avg
// pool per graph -> dense(32->2) -> softmax.
// Round 16: layer-2 GEMM on tensor cores with TF32 (m16n8k8) instead of bf16
// (R15 failed at 3.4e-3 purely from bf16 activation rounding; tf32's 10-bit
// mantissa cuts that ~8x). A1 stays fp32; agg<128> is the R14 champion
// version. Everything else identical to the 208.2us champion.
// ---------------------------------------------------------------------------

#define NN 50000
#define EE 800000
#define GG 256
#define SCAN_B 1024
#define SCAN_NB ((NN + SCAN_B - 1) / SCAN_B)   // 49

// Scratch (device globals; no allocation allowed).
__device__ __nv_bfloat16 g_h[NN * 128];  // h = x @ W1 (bf16, gathered)
__device__ float g_a1[NN * 128];   // layer1 xW2+b -> in-place layer1 output
__device__ float g_a2[NN * 64];    // layer2 base / in-place output
__device__ float g_a3[NN * 32];    // layer3 base (consumed by fused pool)
__device__ float g_pool[GG * 32];
__device__ float g_cnt [GG];

// CSR scratch
__device__ int   g_deg [NN];
__device__ int   g_rp  [NN + 1];
__device__ int   g_cur [NN];
__device__ int   g_bsum[SCAN_NB];
__device__ int   g_ssrc[EE];
__device__ float g_sw  [EE];

// ---- f32x2 packed helpers -------------------------------------------------
__device__ __forceinline__ unsigned long long pk2(float a, float b) {
    unsigned long long r;
    asm("mov.b64 %0, {%1, %2};" : "=l"(r) : "f"(a), "f"(b));
    return r;
}
__device__ __forceinline__ void fma2(unsigned long long& d,
                                     unsigned long long a,
                                     unsigned long long b) {
    asm("fma.rn.f32x2 %0, %1, %2, %0;" : "+l"(d) : "l"(a), "l"(b));
}
__device__ __forceinline__ void upk2(float& lo, float& hi, unsigned long long v) {
    asm("mov.b64 {%0, %1}, %2;" : "=f"(lo), "=f"(hi) : "l"(v));
}

// ---------------------------------------------------------------------------
// Dual GEMM (layers 1, 3): H = bf16(X@W1) ; A = X@W2 + b   (champion config)
// ---------------------------------------------------------------------------
template <int FIN, int FOUT>
__global__ void __launch_bounds__(256, 3) gemm_dual(
    const float* __restrict__ X,
    const float* __restrict__ W1,
    const float* __restrict__ W2,
    const float* __restrict__ Bv,
    __nv_bfloat16* __restrict__ H,
    float* __restrict__ A,
    int n)
{
    constexpr int TPR = FOUT / 4;
    constexpr int RG  = 256 / TPR;
    constexpr int R   = 4;
    constexpr int KV  = 2;

    extern __shared__ float sm[];
    float* sW1 = sm;
    float* sW2 = sm + FIN * FOUT;
    float* sB  = sm + 2 * FIN * FOUT;

    for (int i = threadIdx.x; i < FIN * FOUT; i += 256) {
        sW1[i] = W1[i];
        sW2[i] = W2[i];
    }
    for (int i = threadIdx.x; i < FOUT; i += 256) sB[i] = Bv[i];
    __syncthreads();

    const int c4   = (threadIdx.x % TPR) * 4;
    const int rg   = threadIdx.x / TPR;
    const int row0 = (blockIdx.x * RG + rg) * R;
    if (row0 >= n) return;

    unsigned long long acc1[R][2], acc2[R][2];
#pragma unroll
    for (int r = 0; r < R; r++) {
        acc1[r][0] = 0ull; acc1[r][1] = 0ull;
        acc2[r][0] = 0ull; acc2[r][1] = 0ull;
    }

    const bool full = (row0 + R <= n);

    for (int k0 = 0; k0 < FIN; k0 += KV) {
        unsigned long long w1a[KV], w1b[KV], w2a[KV], w2b[KV];
#pragma unroll
        for (int j = 0; j < KV; j++) {
            const ulonglong2 p1 = *(const ulonglong2*)&sW1[(k0 + j) * FOUT + c4];
            const ulonglong2 p2 = *(const ulonglong2*)&sW2[(k0 + j) * FOUT + c4];
            w1a[j] = p1.x; w1b[j] = p1.y;
            w2a[j] = p2.x; w2b[j] = p2.y;
        }
#pragma unroll
        for (int r = 0; r < R; r++) {
            if (!full && row0 + r >= n) break;
            const float2 q = *(const float2*)&X[(size_t)(row0 + r) * FIN + k0];
            float xv[KV];
            xv[0] = q.x; xv[1] = q.y;
#pragma unroll
            for (int j = 0; j < KV; j++) {
                const unsigned long long xx = pk2(xv[j], xv[j]);
                fma2(acc1[r][0], xx, w1a[j]);
                fma2(acc1[r][1], xx, w1b[j]);
                fma2(acc2[r][0], xx, w2a[j]);
                fma2(acc2[r][1], xx, w2b[j]);
            }
        }
    }

    const float4 bb = *(const float4*)&sB[c4];
#pragma unroll
    for (int r = 0; r < R; r++) {
        int row = row0 + r;
        if (row < n) {
            float4 o1, o2;
            upk2(o1.x, o1.y, acc1[r][0]);
            upk2(o1.z, o1.w, acc1[r][1]);
            upk2(o2.x, o2.y, acc2[r][0]);
            upk2(o2.z, o2.w, acc2[r][1]);
            o2.x += bb.x; o2.y += bb.y; o2.z += bb.z; o2.w += bb.w;
            __nv_bfloat162 h01 = __floats2bfloat162_rn(o1.x, o1.y);
            __nv_bfloat162 h23 = __floats2bfloat162_rn(o1.z, o1.w);
            uint2 hp;
            hp.x = *(const unsigned*)&h01;
            hp.y = *(const unsigned*)&h23;
            *(uint2*)&H[(size_t)row * FOUT + c4] = hp;
            *(float4*)&A[(size_t)row * FOUT + c4] = o2;
        }
    }
}

// ---------------------------------------------------------------------------
// Layer-2 tensor-core GEMM (TF32): C[n,128] = A1[n,128] @ [W1|W2][128,128]
//   cols 0..63   -> H2 = bf16(C)
//   cols 64..127 -> A2 = C + b  (f32)
// mma.sync.aligned.m16n8k8.row.col.f32.tf32.tf32.f32; fp32/tf32 smem tiles
// with stride-132 padding (banks (4g+t)%32, conflict-free fragment loads).
// ---------------------------------------------------------------------------
__device__ __forceinline__ void mma1688(float* c,
    uint32_t a0, uint32_t a1, uint32_t a2, uint32_t a3,
    uint32_t b0, uint32_t b1)
{
    asm volatile(
        "mma.sync.aligned.m16n8k8.row.col.f32.tf32.tf32.f32 "
        "{%0,%1,%2,%3},{%4,%5,%6,%7},{%8,%9},{%0,%1,%2,%3};"
        : "+f"(c[0]), "+f"(c[1]), "+f"(c[2]), "+f"(c[3])
        : "r"(a0), "r"(a1), "r"(a2), "r"(a3), "r"(b0), "r"(b1));
}

__device__ __forceinline__ uint32_t f2tf32(float v) {
    uint32_t t;
    asm("cvt.rna.tf32.f32 %0, %1;" : "=r"(t) : "f"(v));
    return t;
}

#define TF_STR 132   // padded smem row stride in 4B words

__global__ void __launch_bounds__(256) gemm2_mma(
    const float* __restrict__ A1,            // [n,128] fp32
    const float* __restrict__ W1,            // [128,64]
    const float* __restrict__ W2,            // [128,64]
    const float* __restrict__ Bv,            // [64]
    __nv_bfloat16* __restrict__ H,           // [n,64]
    float* __restrict__ A2,                  // [n,64]
    int n)
{
    extern __shared__ uint32_t smem_u[];
    uint32_t* sA = smem_u;                   // [128][TF_STR]
    uint32_t* sW = smem_u + 128 * TF_STR;    // transposed: sW[c][k]

    const int tid  = threadIdx.x;
    const int row0 = blockIdx.x * 128;

    // Stage W transposed + tf32-converted: sW[c][k] = tf32(Wcat[k][c])
    for (int idx = tid; idx < 128 * 128; idx += 256) {
        int c = idx >> 7, k = idx & 127;
        float v = (c < 64) ? __ldg(&W1[k * 64 + c]) : __ldg(&W2[k * 64 + (c - 64)]);
        sW[c * TF_STR + k] = f2tf32(v);
    }
    // Stage A rows, tf32-converted, zero-pad beyond n
    for (int idx = tid; idx < 128 * 128; idx += 256) {
        int r = idx >> 7, k = idx & 127;
        float v = (row0 + r < n) ? __ldg(&A1[(size_t)(row0 + r) * 128 + k]) : 0.f;
        sA[r * TF_STR + k] = f2tf32(v);
    }
    __syncthreads();

    const int warp = tid >> 5, lane = tid & 31;
    const int g = lane >> 2, t = lane & 3;
    const int arow = warp * 16 + g;

    float acc[16][4];
#pragma unroll
    for (int i = 0; i < 16; i++) {
        acc[i][0] = 0.f; acc[i][1] = 0.f; acc[i][2] = 0.f; acc[i][3] = 0.f;
    }

#pragma unroll 4
    for (int k8 = 0; k8 < 16; k8++) {
        const int kb = k8 * 8;
        uint32_t a0 = sA[arow * TF_STR + kb + t];
        uint32_t a1 = sA[(arow + 8) * TF_STR + kb + t];
        uint32_t a2 = sA[arow * TF_STR + kb + t + 4];
        uint32_t a3 = sA[(arow + 8) * TF_STR + kb + t + 4];
#pragma unroll
        for (int nt = 0; nt < 16; nt++) {
            uint32_t b0 = sW[(nt * 8 + g) * TF_STR + kb + t];
            uint32_t b1 = sW[(nt * 8 + g) * TF_STR + kb + t + 4];
            mma1688(acc[nt], a0, a1, a2, a3, b0, b1);
        }
    }

    // Epilogue (C layout: c0/c1 at row arow cols 2t,2t+1; c2/c3 at arow+8)
    const int r_lo = row0 + arow;
    const int r_hi = r_lo + 8;
#pragma unroll
    for (int nt = 0; nt < 16; nt++) {
        int col = nt * 8 + t * 2;
        if (col < 64) {
            __nv_bfloat162 p0 = __floats2bfloat162_rn(acc[nt][0], acc[nt][1]);
            __nv_bfloat162 p1 = __floats2bfloat162_rn(acc[nt][2], acc[nt][3]);
            if (r_lo < n) *(__nv_bfloat162*)&H[(size_t)r_lo * 64 + col] = p0;
            if (r_hi < n) *(__nv_bfloat162*)&H[(size_t)r_hi * 64 + col] = p1;
        } else {
            int c2 = col - 64;
            float b0v = __ldg(&Bv[c2]), b1v = __ldg(&Bv[c2 + 1]);
            if (r_lo < n) {
                float2 o = make_float2(acc[nt][0] + b0v, acc[nt][1] + b1v);
                *(float2*)&A2[(size_t)r_lo * 64 + c2] = o;
            }
            if (r_hi < n) {
                float2 o = make_float2(acc[nt][2] + b0v, acc[nt][3] + b1v);
                *(float2*)&A2[(size_t)r_hi * 64 + c2] = o;
            }
        }
    }
}

// ---------------------------------------------------------------------------
// CSR build kernels
// ---------------------------------------------------------------------------
__global__ void zero_misc_kernel(int n)
{
    int i = blockIdx.x * blockDim.x + threadIdx.x;
    if (i < n)       g_deg[i] = 0;
    if (i < GG * 32) g_pool[i] = 0.f;
    if (i < GG)      g_cnt[i]  = 0.f;
}

__global__ void hist_kernel(const int* __restrict__ er, int E)
{
    int e = blockIdx.x * blockDim.x + threadIdx.x;
    if (e < E) atomicAdd(&g_deg[__ldg(&er[e])], 1);
}

__global__ void __launch_bounds__(SCAN_B) scan1_kernel(int n)
{
    __shared__ int wsum[32];
    int i = blockIdx.x * SCAN_B + threadIdx.x;
    int v = (i < n) ? g_deg[i] : 0;
    int lane = threadIdx.x & 31, wid = threadIdx.x >> 5;

    int s = v;
#pragma unroll
    for (int o = 1; o < 32; o <<= 1) {
        int t = __shfl_up_sync(0xFFFFFFFFu, s, o);
        if (lane >= o) s += t;
    }
    if (lane == 31) wsum[wid] = s;
    __syncthreads();
    if (wid == 0) {
        int ws = wsum[lane];
#pragma unroll
        for (int o = 1; o < 32; o <<= 1) {
            int t = __shfl_up_sync(0xFFFFFFFFu, ws, o);
            if (lane >= o) ws += t;
        }
        wsum[lane] = ws;
    }
    __syncthreads();
    int excl = s - v + ((wid > 0) ? wsum[wid - 1] : 0);
    if (i < n) g_rp[i] = excl;
    if (threadIdx.x == 0) g_bsum[blockIdx.x] = wsum[31];
}

__global__ void __launch_bounds__(SCAN_B) scan3_kernel(int n, int E)
{
    __shared__ int pfx;
    if (threadIdx.x < 32) {
        int s = 0;
        for (int j = threadIdx.x; j < blockIdx.x; j += 32) s += g_bsum[j];
#pragma unroll
        for (int o = 16; o > 0; o >>= 1)
            s += __shfl_xor_sync(0xFFFFFFFFu, s, o);
        if (threadIdx.x == 0) pfx = s;
    }
    __syncthreads();
    int i = blockIdx.x * SCAN_B + threadIdx.x;
    if (i < n) {
        int v = g_rp[i] + pfx;
        g_rp[i]  = v;
        g_cur[i] = v;
    }
    if (blockIdx.x == 0 && threadIdx.x == 0) g_rp[n] = E;
}

__global__ void fill_kernel(const int* __restrict__ er,
                            const int* __restrict__ ec,
                            const float* __restrict__ ew, int E)
{
    int e = blockIdx.x * blockDim.x + threadIdx.x;
    if (e >= E) return;
    int r   = __ldg(&er[e]);
    int pos = atomicAdd(&g_cur[r], 1);
    g_ssrc[pos] = __ldg(&ec[e]);
    g_sw[pos]   = __ldg(&ew[e]);
}

// ---------------------------------------------------------------------------
// Gather aggregation (R14 champion): one warp per destination row.
//   out[r,:] = relu( sum w_e * bf16->f32(H[src,:]) + A[r,:] )
// ---------------------------------------------------------------------------
template <int FOUT, bool POOL>
__global__ void __launch_bounds__(256) agg_rows(
    const __nv_bfloat16* __restrict__ H,
    float* __restrict__ A,
    const int* __restrict__ seg,
    int n)
{
    constexpr int TPR = FOUT / 4;
    constexpr int EPI = 32 / TPR;

    int warp = (blockIdx.x * blockDim.x + threadIdx.x) >> 5;
    if (warp >= n) return;
    int lane = threadIdx.x & 31;
    int cl   = lane % TPR;
    int es   = lane / TPR;

    int begin = __ldg(&g_rp[warp]);
    int end   = __ldg(&g_rp[warp + 1]);

    float4 acc = make_float4(0.f, 0.f, 0.f, 0.f);
#pragma unroll 2
    for (int i = begin + es; i < end; i += EPI) {
        int   src = __ldg(&g_ssrc[i]);
        float w   = __ldg(&g_sw[i]);
        const uint2 hp = *(const uint2*)&H[(size_t)src * FOUT + cl * 4];
        float2 f01 = __bfloat1622float2(*(const __nv_bfloat162*)&hp.x);
        float2 f23 = __bfloat1622float2(*(const __nv_bfloat162*)&hp.y);
        acc.x = fmaf(w, f01.x, acc.x);
        acc.y = fmaf(w, f01.y, acc.y);
        acc.z = fmaf(w, f23.x, acc.z);
        acc.w = fmaf(w, f23.y, acc.w);
    }

#pragma unroll
    for (int off = TPR; off < 32; off <<= 1) {
        acc.x += __shfl_xor_sync(0xFFFFFFFFu, acc.x, off);
        acc.y += __shfl_xor_sync(0xFFFFFFFFu, acc.y, off);
        acc.z += __shfl_xor_sync(0xFFFFFFFFu, acc.z, off);
        acc.w += __shfl_xor_sync(0xFFFFFFFFu, acc.w, off);
    }

    if (es == 0) {
        const float4 base = *(const float4*)&A[(size_t)warp * FOUT + cl * 4];
        float4 o;
        o.x = fmaxf(acc.x + base.x, 0.f);
        o.y = fmaxf(acc.y + base.y, 0.f);
        o.z = fmaxf(acc.z + base.z, 0.f);
        o.w = fmaxf(acc.w + base.w, 0.f);
        if (POOL) {
            int g = __ldg(&seg[warp]);
            float* dst = &g_pool[g * 32 + cl * 4];
            asm volatile("red.global.add.v4.f32 [%0], {%1,%2,%3,%4};"
                         :: "l"(dst), "f"(o.x), "f"(o.y), "f"(o.z), "f"(o.w)
                         : "memory");
            if (cl == 0) atomicAdd(&g_cnt[g], 1.0f);
        } else {
            *(float4*)&A[(size_t)warp * FOUT + cl * 4] = o;
        }
    }
}

__global__ void head_kernel(const float* __restrict__ wd,
                            const float* __restrict__ bd,
                            float* __restrict__ out)
{
    int g = threadIdx.x;
    float cnt = fmaxf(g_cnt[g], 1.0f);
    float inv = 1.0f / cnt;
    float z0 = __ldg(&bd[0]);
    float z1 = __ldg(&bd[1]);
#pragma unroll
    for (int k = 0; k < 32; k++) {
        float p = g_pool[g * 32 + k] * inv;
        z0 = fmaf(p, __ldg(&wd[k * 2 + 0]), z0);
        z1 = fmaf(p, __ldg(&wd[k * 2 + 1]), z1);
    }
    float m  = fmaxf(z0, z1);
    float e0 = __expf(z0 - m);
    float e1 = __expf(z1 - m);
    float s  = 1.0f / (e0 + e1);
    out[g * 2 + 0] = e0 * s;
    out[g * 2 + 1] = e1 * s;
}

// ---------------------------------------------------------------------------
// Launch: CSR fork + tf32 tensor-core layer 2.
// ---------------------------------------------------------------------------
extern "C" void kernel_launch(void* const* d_in, const int* in_sizes, int n_in,
                              void* d_out, int out_size)
{
    const float* x    = (const float*)d_in[0];
    const float* ew   = (const float*)d_in[1];
    const int*   er   = (const int*)  d_in[2];
    const int*   ec   = (const int*)  d_in[3];
    const int*   seg  = (const int*)  d_in[4];
    const float* w1_1 = (const float*)d_in[5];
    const float* w2_1 = (const float*)d_in[6];
    const float* b_1  = (const float*)d_in[7];
    const float* w1_2 = (const float*)d_in[8];
    const float* w2_2 = (const float*)d_in[9];
    const float* b_2  = (const float*)d_in[10];
    const float* w1_3 = (const float*)d_in[11];
    const float* w2_3 = (const float*)d_in[12];
    const float* b_3  = (const float*)d_in[13];
    const float* wd   = (const float*)d_in[14];
    const float* bd   = (const float*)d_in[15];
    float* out = (float*)d_out;

    const int n = in_sizes[0] / 30;   // 50000
    const int E = in_sizes[1];        // 800000

    __nv_bfloat16* H;
    float *A1, *A2, *A3;
    cudaGetSymbolAddress((void**)&H,  g_h);
    cudaGetSymbolAddress((void**)&A1, g_a1);
    cudaGetSymbolAddress((void**)&A2, g_a2);
    cudaGetSymbolAddress((void**)&A3, g_a3);

    // Side stream + events (created once; identical behavior every call).
    static cudaStream_t sB = nullptr;
    static cudaEvent_t  evFork = nullptr, evCSR = nullptr;
    if (sB == nullptr) {
        cudaStreamCreateWithFlags(&sB, cudaStreamNonBlocking);
        cudaEventCreateWithFlags(&evFork, cudaEventDisableTiming);
        cudaEventCreateWithFlags(&evCSR,  cudaEventDisableTiming);
    }

    const int sm1 = (2 * 30 * 128 + 128) * 4;   // layer-1 dual GEMM smem
    const int sm3 = (2 * 64 * 32  + 32) * 4;    // layer-3 dual GEMM smem
    const int smMMA = 2 * 128 * TF_STR * 4;     // 135168B: A-tile + W-tile

    cudaFuncSetAttribute(gemm2_mma,
                         cudaFuncAttributeMaxDynamicSharedMemorySize, smMMA);

    const int agg_blocks = (n * 32 + 255) / 256;

    // ---- Fork: CSR build on side stream ----
    cudaEventRecord(evFork, 0);
    cudaStreamWaitEvent(sB, evFork, 0);
    zero_misc_kernel<<<(n + 255) / 256, 256, 0, sB>>>(n);
    hist_kernel<<<(E + 255) / 256, 256, 0, sB>>>(er, E);
    scan1_kernel<<<SCAN_NB, SCAN_B, 0, sB>>>(n);
    scan3_kernel<<<SCAN_NB, SCAN_B, 0, sB>>>(n, E);
    fill_kernel<<<(E + 255) / 256, 256, 0, sB>>>(er, ec, ew, E);
    cudaEventRecord(evCSR, sB);

    // ---- Main stream: layer-1 GEMM overlaps the CSR build ----
    {
        int rows_per_block = (256 / (128 / 4)) * 4;  // 32
        int blocks = (n + rows_per_block - 1) / rows_per_block;
        gemm_dual<30, 128><<<blocks, 256, sm1>>>(x, w1_1, w2_1, b_1, H, A1, n);
    }

    // ---- Join; layer-1 aggregation (f32 in-place, champion path) ----
    cudaStreamWaitEvent(0, evCSR, 0);
    agg_rows<128, false><<<agg_blocks, 256>>>(H, A1, seg, n);

    // ---- Layer 2: tf32 tensor-core GEMM (dual output + bias fused) ----
    gemm2_mma<<<(n + 127) / 128, 256, smMMA>>>(A1, w1_2, w2_2, b_2, H, A2, n);
    agg_rows<64, false><<<agg_blocks, 256>>>(H, A2, seg, n);

    // ---- Layer 3: 64 -> 32 (champion scalar path; agg fuses relu + pool) ----
    {
        int rows_per_block = (256 / (32 / 4)) * 4;   // 128
        int blocks = (n + rows_per_block - 1) / rows_per_block;
        gemm_dual<64, 32><<<blocks, 256, sm3>>>(A2, w1_3, w2_3, b_3, H, A3, n);
        agg_rows<32, true><<<agg_blocks, 256>>>(H, A3, seg, n);
    }

    // ---- Head ----
    head_kernel<<<1, GG>>>(wd, bd, out);
}